// round 13
// baseline (speedup 1.0000x reference)
#include <cuda_runtime.h>
#include <cstdint>

#define B_   256
#define T_   2048
#define IN_  128
#define H_   64
#define G_   256   // 4*H

// Scratch (allocation-free rule: static __device__ array)
__device__ float g_xp[(size_t)B_ * T_ * G_];   // precomputed x@W_ih1^T + b_ih1 + b_hh1

typedef unsigned long long u64;

// ---------------- helpers ----------------
__device__ __forceinline__ void ffma2(u64& d, u64 a, u64 b) {
    asm("fma.rn.f32x2 %0, %1, %2, %0;" : "+l"(d) : "l"(a), "l"(b));
}
__device__ __forceinline__ float2 unpk(u64 p) {
    float2 r;
    asm("mov.b64 {%0, %1}, %2;" : "=f"(r.x), "=f"(r.y) : "l"(p));
    return r;
}
__device__ __forceinline__ float tanh_hw(float x) {
    float r;
    asm("tanh.approx.f32 %0, %1;" : "=f"(r) : "f"(x));
    return r;
}
__device__ __forceinline__ float sig_hw(float x) {
    return fmaf(0.5f, tanh_hw(0.5f * x), 0.5f);
}

// ---------------- kernel 1: xp = x @ W_ih1^T + b_ih1 + b_hh1 ----------------
// (unchanged from R8 — W tile staged in smem, broadcast LDG.128 for x)
__global__ __launch_bounds__(256) void xp_gemm(const float* __restrict__ x,
                                               const float* __restrict__ W,
                                               const float* __restrict__ bih,
                                               const float* __restrict__ bhh) {
    __shared__ float Ws[64][132];              // 33 KB
    int tid = threadIdx.x;
    size_t mbase = (size_t)blockIdx.x * 64;
    int nbase = blockIdx.y * 64;

#pragma unroll
    for (int i = 0; i < 8; i++) {
        int idx = tid + i * 256;
        int r = idx >> 5, c4 = (idx & 31) << 2;
        *(float4*)&Ws[r][c4] = *(const float4*)(W + (size_t)(nbase + r) * IN_ + c4);
    }
    __syncthreads();

    int tx = tid & 15, ty = tid >> 4;
    int m0 = ty * 4;
    const float* xg = x + (mbase + m0) * IN_;

    u64 acc[4][4];
#pragma unroll
    for (int i = 0; i < 4; i++)
#pragma unroll
        for (int j = 0; j < 4; j++) acc[i][j] = 0ull;

#pragma unroll 4
    for (int k4 = 0; k4 < IN_; k4 += 4) {
        u64 wv[4][2];
#pragma unroll
        for (int j = 0; j < 4; j++) {
            ulonglong2 t2 = *(const ulonglong2*)&Ws[tx + 16 * j][k4];
            wv[j][0] = t2.x; wv[j][1] = t2.y;
        }
#pragma unroll
        for (int i = 0; i < 4; i++) {
            ulonglong2 xv = *(const ulonglong2*)(xg + (size_t)i * IN_ + k4);
#pragma unroll
            for (int j = 0; j < 4; j++) {
                ffma2(acc[i][j], xv.x, wv[j][0]);
                ffma2(acc[i][j], xv.y, wv[j][1]);
            }
        }
    }

#pragma unroll
    for (int j = 0; j < 4; j++) {
        int n = nbase + tx + 16 * j;
        float b = bih[n] + bhh[n];
#pragma unroll
        for (int i = 0; i < 4; i++) {
            float2 p = unpk(acc[i][j]);
            g_xp[(mbase + m0 + i) * G_ + n] = p.x + p.y + b;
        }
    }
}

// ---------------- kernel 2: fused 2-layer LSTM, LAYER-LAGGED pipeline ----------------
// 128 CTAs x 256 threads, 2 batch rows per CTA. Thread (q=tid>>2: unit, s=tid&3: k-split).
// Layer 2 runs ONE STEP BEHIND layer 1:
//   iter t (t = 0..T inclusive):
//     dots (single fused pass, all inputs pre-barrier state):
//       b = W1 *h1(t-1)            -> wv1 -> cell1 -> h1(t)      [skip t=T]
//       a = W2i*h1(t-1) + W2h*h2(t-2) -> wv2 -> cell2 -> h2(t-1) [zero at t=0]
//     head p(t-1) -> red[par]; store h1s[par], h2s[par]
//     lagged out(t-2) written at TOP of iter t from red[prv]
//     ONE __syncthreads per iter.
__global__ __launch_bounds__(256, 1) void lstm_rec(
    const float* __restrict__ Whh1, const float* __restrict__ Wih2,
    const float* __restrict__ Whh2, const float* __restrict__ bih2,
    const float* __restrict__ bhh2, const float* __restrict__ Wout,
    const float* __restrict__ bout, float* __restrict__ out) {
    __shared__ float h1s[2][2][64];   // [parity][row][unit]
    __shared__ float h2s[2][2][64];
    __shared__ float red[2][16];      // [parity][warp*2+row]

    int tid = threadIdx.x;
    int q = tid >> 2, s = tid & 3;
    int myrow = s & 1;

    // ---- weights into registers (gate-interleaved rows, k in [16s,16s+16)) ----
    u64 w1[4][8], w2i[4][8], w2h[4][8];
#pragma unroll
    for (int g = 0; g < 4; g++) {
        const u64* p;
        p = (const u64*)(Whh1 + (size_t)(g * 64 + q) * 64 + s * 16);
#pragma unroll
        for (int j = 0; j < 8; j++) w1[g][j] = p[j];
        p = (const u64*)(Wih2 + (size_t)(g * 64 + q) * 64 + s * 16);
#pragma unroll
        for (int j = 0; j < 8; j++) w2i[g][j] = p[j];
        p = (const u64*)(Whh2 + (size_t)(g * 64 + q) * 64 + s * 16);
#pragma unroll
        for (int j = 0; j < 8; j++) w2h[g][j] = p[j];
    }
    float b2v = bih2[s * 64 + q] + bhh2[s * 64 + q];   // bias of gate s*64+q
    float wo = Wout[q];
    float bo = bout[0];
    float c1 = 0.0f, c2 = 0.0f;                        // carries for row = myrow

    int b0 = blockIdx.x * 2;
    const float* xp0 = g_xp + (size_t)b0 * T_ * G_ + s * 64 + q;   // gate s*64+q
    const float* xp1 = xp0 + (size_t)T_ * G_;
    float xq0 = xp0[0];                                // xp(0)
    float xq1 = xp1[0];

    if (tid < 128) {                  // zero parity-1 (prv at iter 0)
        h1s[1][tid >> 6][tid & 63] = 0.0f;
        h2s[1][tid >> 6][tid & 63] = 0.0f;
    }
    __syncthreads();

    for (int t = 0; t <= T_; t++) {
        int par = t & 1, prv = par ^ 1;

        // ---- lagged output write: out(t-2) from red[prv] (written iter t-1) ----
        if (t >= 2 && tid < 2) {
            float r = bo;
#pragma unroll
            for (int w = 0; w < 8; w++) r += red[prv][w * 2 + tid];
            r = fminf(fmaxf(r, 0.0f), 1.0f);
            out[(size_t)(b0 + tid) * T_ + (t - 2)] = r;
        }

        // ---- fused triple-dot pass (all pre-barrier state) ----
        u64 a[8], b[8];   // [2*gate + row]
#pragma unroll
        for (int i = 0; i < 8; i++) { a[i] = 0ull; b[i] = 0ull; }
        {
            const ulonglong2* h1A = (const ulonglong2*)&h1s[prv][0][s * 16];
            const ulonglong2* h1B = (const ulonglong2*)&h1s[prv][1][s * 16];
            const ulonglong2* h2A = (const ulonglong2*)&h2s[prv][0][s * 16];
            const ulonglong2* h2B = (const ulonglong2*)&h2s[prv][1][s * 16];
#pragma unroll
            for (int j = 0; j < 4; j++) {
                ulonglong2 u0 = h1A[j];
                ulonglong2 u1 = h1B[j];
#pragma unroll
                for (int g = 0; g < 4; g++) {
                    ffma2(b[2 * g + 0], w1[g][2 * j], u0.x);
                    ffma2(b[2 * g + 0], w1[g][2 * j + 1], u0.y);
                    ffma2(b[2 * g + 1], w1[g][2 * j], u1.x);
                    ffma2(b[2 * g + 1], w1[g][2 * j + 1], u1.y);
                }
#pragma unroll
                for (int g = 0; g < 4; g++) {
                    ffma2(a[2 * g + 0], w2i[g][2 * j], u0.x);
                    ffma2(a[2 * g + 0], w2i[g][2 * j + 1], u0.y);
                    ffma2(a[2 * g + 1], w2i[g][2 * j], u1.x);
                    ffma2(a[2 * g + 1], w2i[g][2 * j + 1], u1.y);
                }
                ulonglong2 z0 = h2A[j];
                ulonglong2 z1 = h2B[j];
#pragma unroll
                for (int g = 0; g < 4; g++) {
                    ffma2(a[2 * g + 0], w2h[g][2 * j], z0.x);
                    ffma2(a[2 * g + 0], w2h[g][2 * j + 1], z0.y);
                    ffma2(a[2 * g + 1], w2h[g][2 * j], z1.x);
                    ffma2(a[2 * g + 1], w2h[g][2 * j + 1], z1.y);
                }
            }
        }

        // ---- reduce b -> wv1(t) (xp(t) folded, lane s==g only) ----
        float wv1[4], wv2[4];
#pragma unroll
        for (int g = 0; g < 4; g++) {
            float2 f0 = unpk(b[2 * g + 0]);
            float2 f1 = unpk(b[2 * g + 1]);
            float v0 = f0.x + f0.y + ((s == g) ? xq0 : 0.0f);
            float v1 = f1.x + f1.y + ((s == g) ? xq1 : 0.0f);
            float snd = myrow ? v0 : v1;
            float own = myrow ? v1 : v0;
            float tt = own + __shfl_xor_sync(0xffffffffu, snd, 1);
            tt += __shfl_xor_sync(0xffffffffu, tt, 2);
            wv1[g] = tt;
        }
        // ---- reduce a -> wv2(t-1) (bias2 folded, lane s==g only) ----
#pragma unroll
        for (int g = 0; g < 4; g++) {
            float bb = (s == g) ? b2v : 0.0f;
            float2 f0 = unpk(a[2 * g + 0]);
            float2 f1 = unpk(a[2 * g + 1]);
            float v0 = f0.x + f0.y + bb;
            float v1 = f1.x + f1.y + bb;
            float snd = myrow ? v0 : v1;
            float own = myrow ? v1 : v0;
            float tt = own + __shfl_xor_sync(0xffffffffu, snd, 1);
            tt += __shfl_xor_sync(0xffffffffu, tt, 2);
            wv2[g] = tt;
        }

        // prefetch xp(t+1) (consumed next iter, >= 1 barrier away)
        if (t + 1 < T_) {
            xp0 += G_; xp1 += G_;
            xq0 = *xp0;
            xq1 = *xp1;
        }

        // ---- cell-1 -> h1(t)  [skip at t=T] ----
        if (t < T_) {
            float iv = sig_hw(wv1[0]), fv = sig_hw(wv1[1]);
            float gv = tanh_hw(wv1[2]), ov = sig_hw(wv1[3]);
            c1 = fv * c1 + iv * gv;
            float h1v = ov * tanh_hw(c1);
            if (s < 2) h1s[par][s][q] = h1v;
        }

        // ---- cell-2 -> h2(t-1)  [zero at t=0] + head partials ----
        float h2v;
        if (t > 0) {
            float iv = sig_hw(wv2[0]), fv = sig_hw(wv2[1]);
            float gv = tanh_hw(wv2[2]), ov = sig_hw(wv2[3]);
            c2 = fv * c2 + iv * gv;
            h2v = ov * tanh_hw(c2);
        } else {
            h2v = 0.0f;
        }
        if (s < 2) h2s[par][s][q] = h2v;
        {
            float p = wo * h2v;
            p += __shfl_xor_sync(0xffffffffu, p, 4);
            p += __shfl_xor_sync(0xffffffffu, p, 8);
            p += __shfl_xor_sync(0xffffffffu, p, 16);
            if ((tid & 31) < 2) red[par][(tid >> 5) * 2 + s] = p;
        }
        __syncthreads();              // THE barrier
    }

    // epilogue: out(T-1) from red[T&1] (p(T-1) written at iter t=T)
    if (tid < 2) {
        float r = bo;
#pragma unroll
        for (int w = 0; w < 8; w++) r += red[T_ & 1][w * 2 + tid];
        r = fminf(fmaxf(r, 0.0f), 1.0f);
        out[(size_t)(b0 + tid) * T_ + (T_ - 1)] = r;
    }
}

// ---------------- launch ----------------
extern "C" void kernel_launch(void* const* d_in, const int* in_sizes, int n_in,
                              void* d_out, int out_size) {
    const float* x    = (const float*)d_in[0];
    const float* Wih1 = (const float*)d_in[1];
    const float* Whh1 = (const float*)d_in[2];
    const float* bih1 = (const float*)d_in[3];
    const float* bhh1 = (const float*)d_in[4];
    const float* Wih2 = (const float*)d_in[5];
    const float* Whh2 = (const float*)d_in[6];
    const float* bih2 = (const float*)d_in[7];
    const float* bhh2 = (const float*)d_in[8];
    const float* Wout = (const float*)d_in[9];
    const float* bout = (const float*)d_in[10];
    float* out = (float*)d_out;

    xp_gemm<<<dim3((B_ * T_) / 64, G_ / 64), 256>>>(x, Wih1, bih1, bhh1);
    lstm_rec<<<128, 256>>>(Whh1, Wih2, Whh2, bih2, bhh2, Wout, bout, out);
    (void)in_sizes; (void)n_in; (void)out_size;
}

// round 14
// speedup vs baseline: 1.0953x; 1.0953x over previous
#include <cuda_runtime.h>
#include <cstdint>

#define B_   256
#define T_   2048
#define IN_  128
#define H_   64
#define G_   256   // 4*H

// Scratch (allocation-free rule: static __device__ array)
__device__ float g_xp[(size_t)B_ * T_ * G_];   // precomputed x@W_ih1^T + b_ih1 + b_hh1

typedef unsigned long long u64;

// ---------------- helpers ----------------
__device__ __forceinline__ void ffma2(u64& d, u64 a, u64 b) {
    asm("fma.rn.f32x2 %0, %1, %2, %0;" : "+l"(d) : "l"(a), "l"(b));
}
__device__ __forceinline__ float2 unpk(u64 p) {
    float2 r;
    asm("mov.b64 {%0, %1}, %2;" : "=f"(r.x), "=f"(r.y) : "l"(p));
    return r;
}
__device__ __forceinline__ float tanh_hw(float x) {
    float r;
    asm("tanh.approx.f32 %0, %1;" : "=f"(r) : "f"(x));
    return r;
}
__device__ __forceinline__ float sig_hw(float x) {
    return fmaf(0.5f, tanh_hw(0.5f * x), 0.5f);
}

// ---------------- kernel 1: xp = x @ W_ih1^T + b_ih1 + b_hh1 ----------------
// (unchanged from R8 — W tile staged in smem, broadcast LDG.128 for x)
__global__ __launch_bounds__(256) void xp_gemm(const float* __restrict__ x,
                                               const float* __restrict__ W,
                                               const float* __restrict__ bih,
                                               const float* __restrict__ bhh) {
    __shared__ float Ws[64][132];              // 33 KB
    int tid = threadIdx.x;
    size_t mbase = (size_t)blockIdx.x * 64;
    int nbase = blockIdx.y * 64;

#pragma unroll
    for (int i = 0; i < 8; i++) {
        int idx = tid + i * 256;
        int r = idx >> 5, c4 = (idx & 31) << 2;
        *(float4*)&Ws[r][c4] = *(const float4*)(W + (size_t)(nbase + r) * IN_ + c4);
    }
    __syncthreads();

    int tx = tid & 15, ty = tid >> 4;
    int m0 = ty * 4;
    const float* xg = x + (mbase + m0) * IN_;

    u64 acc[4][4];
#pragma unroll
    for (int i = 0; i < 4; i++)
#pragma unroll
        for (int j = 0; j < 4; j++) acc[i][j] = 0ull;

#pragma unroll 4
    for (int k4 = 0; k4 < IN_; k4 += 4) {
        u64 wv[4][2];
#pragma unroll
        for (int j = 0; j < 4; j++) {
            ulonglong2 t2 = *(const ulonglong2*)&Ws[tx + 16 * j][k4];
            wv[j][0] = t2.x; wv[j][1] = t2.y;
        }
#pragma unroll
        for (int i = 0; i < 4; i++) {
            ulonglong2 xv = *(const ulonglong2*)(xg + (size_t)i * IN_ + k4);
#pragma unroll
            for (int j = 0; j < 4; j++) {
                ffma2(acc[i][j], xv.x, wv[j][0]);
                ffma2(acc[i][j], xv.y, wv[j][1]);
            }
        }
    }

#pragma unroll
    for (int j = 0; j < 4; j++) {
        int n = nbase + tx + 16 * j;
        float b = bih[n] + bhh[n];
#pragma unroll
        for (int i = 0; i < 4; i++) {
            float2 p = unpk(acc[i][j]);
            g_xp[(mbase + m0 + i) * G_ + n] = p.x + p.y + b;
        }
    }
}

// ---------------- kernel 2: fused 2-layer LSTM recurrence + output head ----------------
// R12 structure (2 barriers/step, fused P2b+P1(t+1) pass, carried wv1) with:
//  - select-free reduces: accumulators ordered own-row / partner-row via
//    myrow-swapped h and xp pointers; reduce = vo + shfl(vp,1), then shfl( ,2)
//  - time loop unrolled x2 so parities are compile-time constants
__global__ __launch_bounds__(256, 1) void lstm_rec(
    const float* __restrict__ Whh1, const float* __restrict__ Wih2,
    const float* __restrict__ Whh2, const float* __restrict__ bih2,
    const float* __restrict__ bhh2, const float* __restrict__ Wout,
    const float* __restrict__ bout, float* __restrict__ out) {
    __shared__ float h1s[2][2][64];   // [parity][row][unit]
    __shared__ float h2s[2][2][64];
    __shared__ float red[16];         // [warp][row]

    int tid = threadIdx.x;
    int q = tid >> 2, s = tid & 3;
    int myrow = s & 1;
    int prow = myrow ^ 1;

    // ---- weights into registers (gate-interleaved rows, k in [16s,16s+16)) ----
    u64 w1[4][8], w2i[4][8], w2h[4][8];
#pragma unroll
    for (int g = 0; g < 4; g++) {
        const u64* p;
        p = (const u64*)(Whh1 + (size_t)(g * 64 + q) * 64 + s * 16);
#pragma unroll
        for (int j = 0; j < 8; j++) w1[g][j] = p[j];
        p = (const u64*)(Wih2 + (size_t)(g * 64 + q) * 64 + s * 16);
#pragma unroll
        for (int j = 0; j < 8; j++) w2i[g][j] = p[j];
        p = (const u64*)(Whh2 + (size_t)(g * 64 + q) * 64 + s * 16);
#pragma unroll
        for (int j = 0; j < 8; j++) w2h[g][j] = p[j];
    }
    float b2v = bih2[s * 64 + q] + bhh2[s * 64 + q];   // bias of gate s*64+q
    float wo = Wout[q];
    float bo = bout[0];
    float c1 = 0.0f, c2 = 0.0f;                        // carries for row = myrow

    int b0 = blockIdx.x * 2;
    // xp pointers swapped so xqo is always "my row", xqp the partner's
    const float* xprow0 = g_xp + (size_t)b0 * T_ * G_ + s * 64 + q;
    const float* xprow1 = xprow0 + (size_t)T_ * G_;
    const float* xpo = myrow ? xprow1 : xprow0;
    const float* xpp = myrow ? xprow0 : xprow1;
    float xqo = xpo[0];
    float xqp = xpp[0];

    if (tid < 128) {                  // zero parity-1 (prv at t=0)
        h1s[1][tid >> 6][tid & 63] = 0.0f;
        h2s[1][tid >> 6][tid & 63] = 0.0f;
    }
    __syncthreads();

    // ---- prologue: wv1(0). h = 0 so layer-1 gates(0) = xp(0) distributed ----
    float wv1[4];
#pragma unroll
    for (int g = 0; g < 4; g++) {
        float fo = (s == g) ? xqo : 0.0f;
        float fp = (s == g) ? xqp : 0.0f;
        float tt = fo + __shfl_xor_sync(0xffffffffu, fp, 1);
        tt += __shfl_xor_sync(0xffffffffu, tt, 2);
        wv1[g] = tt;
    }

    auto step = [&](const int CUR, const int PRV, const int TT) {
        // ---- cell-1 update from carried wv1 -> h1(TT) ----
        float h1v;
        {
            float iv = sig_hw(wv1[0]), fv = sig_hw(wv1[1]);
            float gv = tanh_hw(wv1[2]), ov = sig_hw(wv1[3]);
            c1 = fv * c1 + iv * gv;
            h1v = ov * tanh_hw(c1);
        }

        // ---- P2a: layer-2 dots over h2 PREV (own/partner ordered) ----
        u64 a[8];   // [2g+0]=own row, [2g+1]=partner row
#pragma unroll
        for (int i = 0; i < 8; i++) a[i] = 0ull;
        {
            const ulonglong2* hO = (const ulonglong2*)&h2s[PRV][myrow][s * 16];
            const ulonglong2* hP = (const ulonglong2*)&h2s[PRV][prow][s * 16];
#pragma unroll
            for (int j = 0; j < 4; j++) {
                ulonglong2 zo = hO[j];
                ulonglong2 zp = hP[j];
#pragma unroll
                for (int g = 0; g < 4; g++) {
                    ffma2(a[2 * g + 0], w2h[g][2 * j], zo.x);
                    ffma2(a[2 * g + 0], w2h[g][2 * j + 1], zo.y);
                    ffma2(a[2 * g + 1], w2h[g][2 * j], zp.x);
                    ffma2(a[2 * g + 1], w2h[g][2 * j + 1], zp.y);
                }
            }
        }
        // prefetch xp(TT+1)
        if (TT + 1 < T_) {
            xpo += G_; xpp += G_;
            xqo = *xpo;
            xqp = *xpp;
        }
        if (s < 2) h1s[CUR][s][q] = h1v;     // lane s stores row s (= its myrow)
        __syncthreads();                     // B1: h1(CUR) visible

        // ---- fused pass over h1 NEW: P2b (into a) + P1(TT+1) (into b) ----
        u64 b[8];
#pragma unroll
        for (int i = 0; i < 8; i++) b[i] = 0ull;
        {
            const ulonglong2* hO = (const ulonglong2*)&h1s[CUR][myrow][s * 16];
            const ulonglong2* hP = (const ulonglong2*)&h1s[CUR][prow][s * 16];
#pragma unroll
            for (int j = 0; j < 4; j++) {
                ulonglong2 uo = hO[j];
                ulonglong2 up = hP[j];
#pragma unroll
                for (int g = 0; g < 4; g++) {
                    ffma2(a[2 * g + 0], w2i[g][2 * j], uo.x);
                    ffma2(a[2 * g + 0], w2i[g][2 * j + 1], uo.y);
                    ffma2(a[2 * g + 1], w2i[g][2 * j], up.x);
                    ffma2(a[2 * g + 1], w2i[g][2 * j + 1], up.y);
                }
#pragma unroll
                for (int g = 0; g < 4; g++) {
                    ffma2(b[2 * g + 0], w1[g][2 * j], uo.x);
                    ffma2(b[2 * g + 0], w1[g][2 * j + 1], uo.y);
                    ffma2(b[2 * g + 1], w1[g][2 * j], up.x);
                    ffma2(b[2 * g + 1], w1[g][2 * j + 1], up.y);
                }
            }
        }

        // ---- reduce a -> wv2(TT)  (bias folded pre-reduction, lane s==g) ----
        float wv2[4];
#pragma unroll
        for (int g = 0; g < 4; g++) {
            float bb = (s == g) ? b2v : 0.0f;
            float2 fo = unpk(a[2 * g + 0]);
            float2 fp = unpk(a[2 * g + 1]);
            float vo = fo.x + fo.y + bb;
            float vp = fp.x + fp.y + bb;
            float tt = vo + __shfl_xor_sync(0xffffffffu, vp, 1);
            tt += __shfl_xor_sync(0xffffffffu, tt, 2);
            wv2[g] = tt;
        }

        // ---- reduce b -> wv1(TT+1)  (xp folded pre-reduction, lane s==g) ----
#pragma unroll
        for (int g = 0; g < 4; g++) {
            float2 fo = unpk(b[2 * g + 0]);
            float2 fp = unpk(b[2 * g + 1]);
            float vo = fo.x + fo.y + ((s == g) ? xqo : 0.0f);
            float vp = fp.x + fp.y + ((s == g) ? xqp : 0.0f);
            float tt = vo + __shfl_xor_sync(0xffffffffu, vp, 1);
            tt += __shfl_xor_sync(0xffffffffu, tt, 2);
            wv1[g] = tt;
        }

        // ---- cell-2 update + output head ----
        {
            float iv = sig_hw(wv2[0]), fv = sig_hw(wv2[1]);
            float gv = tanh_hw(wv2[2]), ov = sig_hw(wv2[3]);
            c2 = fv * c2 + iv * gv;
            float h2v = ov * tanh_hw(c2);
            if (s < 2) h2s[CUR][s][q] = h2v;
            float p = wo * h2v;
            p += __shfl_xor_sync(0xffffffffu, p, 4);
            p += __shfl_xor_sync(0xffffffffu, p, 8);
            p += __shfl_xor_sync(0xffffffffu, p, 16);
            if ((tid & 31) < 2) red[(tid >> 5) * 2 + s] = p;
        }
        __syncthreads();              // B2: h2(CUR) + red visible

        if (tid < 2) {
            float r = bo;
#pragma unroll
            for (int w = 0; w < 8; w++) r += red[w * 2 + tid];
            r = fminf(fmaxf(r, 0.0f), 1.0f);
            out[(size_t)(b0 + tid) * T_ + TT] = r;
        }
    };

    for (int tb = 0; tb < T_; tb += 2) {   // T_ even; parities literal
        step(0, 1, tb);
        step(1, 0, tb + 1);
    }
}

// ---------------- launch ----------------
extern "C" void kernel_launch(void* const* d_in, const int* in_sizes, int n_in,
                              void* d_out, int out_size) {
    const float* x    = (const float*)d_in[0];
    const float* Wih1 = (const float*)d_in[1];
    const float* Whh1 = (const float*)d_in[2];
    const float* bih1 = (const float*)d_in[3];
    const float* bhh1 = (const float*)d_in[4];
    const float* Wih2 = (const float*)d_in[5];
    const float* Whh2 = (const float*)d_in[6];
    const float* bih2 = (const float*)d_in[7];
    const float* bhh2 = (const float*)d_in[8];
    const float* Wout = (const float*)d_in[9];
    const float* bout = (const float*)d_in[10];
    float* out = (float*)d_out;

    xp_gemm<<<dim3((B_ * T_) / 64, G_ / 64), 256>>>(x, Wih1, bih1, bhh1);
    lstm_rec<<<128, 256>>>(Whh1, Wih2, Whh2, bih2, bhh2, Wout, bout, out);
    (void)in_sizes; (void)n_in; (void)out_size;
}

// round 15
// speedup vs baseline: 1.1058x; 1.0096x over previous
#include <cuda_runtime.h>
#include <cstdint>
#include <mma.h>

using namespace nvcuda;

#define B_   256
#define T_   2048
#define IN_  128
#define H_   64
#define G_   256   // 4*H

// Scratch (allocation-free rule: static __device__ array)
__device__ float g_xp[(size_t)B_ * T_ * G_];   // x@W_ih1^T (NO bias — folded in lstm)

typedef unsigned long long u64;

// ---------------- helpers ----------------
__device__ __forceinline__ void ffma2(u64& d, u64 a, u64 b) {
    asm("fma.rn.f32x2 %0, %1, %2, %0;" : "+l"(d) : "l"(a), "l"(b));
}
__device__ __forceinline__ float2 unpk(u64 p) {
    float2 r;
    asm("mov.b64 {%0, %1}, %2;" : "=f"(r.x), "=f"(r.y) : "l"(p));
    return r;
}
__device__ __forceinline__ float tanh_hw(float x) {
    float r;
    asm("tanh.approx.f32 %0, %1;" : "=f"(r) : "f"(x));
    return r;
}
__device__ __forceinline__ float sig_hw(float x) {
    return fmaf(0.5f, tanh_hw(0.5f * x), 0.5f);
}

// ---------------- kernel 1: xp = x @ W_ih1^T  (tf32 tensor cores) ----------------
// M = B*T = 524288, N = 256, K = 128. Grid 4096 blocks x 256 thr (8 warps).
// BM=128 (4 m-warps x 32 rows), BN=256 (2 n-warps x 128 cols).
// Per warp: 2 m-frags x 8 n-frags accumulators; B loaded col_major straight
// from row-major W (W[n][k]: column n contiguous in k, ld=128). W is L1-hot
// across the ~28 sequential blocks per SM (L1 persists within a launch).
__global__ __launch_bounds__(256) void xp_wmma(const float* __restrict__ x,
                                               const float* __restrict__ W) {
    int wid = threadIdx.x >> 5;
    int mwarp = wid >> 1, nwarp = wid & 1;
    size_t mbase = (size_t)blockIdx.x * 128 + mwarp * 32;
    int nbase = nwarp * 128;

    wmma::fragment<wmma::accumulator, 16, 16, 8, float> acc[2][8];
#pragma unroll
    for (int i = 0; i < 2; i++)
#pragma unroll
        for (int j = 0; j < 8; j++) wmma::fill_fragment(acc[i][j], 0.0f);

#pragma unroll
    for (int k = 0; k < IN_; k += 8) {
        wmma::fragment<wmma::matrix_a, 16, 16, 8, wmma::precision::tf32,
                       wmma::row_major> af[2];
        wmma::fragment<wmma::matrix_b, 16, 16, 8, wmma::precision::tf32,
                       wmma::col_major> bf[8];
#pragma unroll
        for (int i = 0; i < 2; i++) {
            wmma::load_matrix_sync(af[i], x + (mbase + i * 16) * IN_ + k, IN_);
#pragma unroll
            for (int e = 0; e < af[i].num_elements; e++)
                af[i].x[e] = wmma::__float_to_tf32(af[i].x[e]);
        }
#pragma unroll
        for (int j = 0; j < 8; j++) {
            wmma::load_matrix_sync(bf[j], W + (size_t)(nbase + j * 16) * IN_ + k, IN_);
#pragma unroll
            for (int e = 0; e < bf[j].num_elements; e++)
                bf[j].x[e] = wmma::__float_to_tf32(bf[j].x[e]);
        }
#pragma unroll
        for (int i = 0; i < 2; i++)
#pragma unroll
            for (int j = 0; j < 8; j++)
                wmma::mma_sync(acc[i][j], af[i], bf[j], acc[i][j]);
    }

#pragma unroll
    for (int i = 0; i < 2; i++)
#pragma unroll
        for (int j = 0; j < 8; j++)
            wmma::store_matrix_sync(g_xp + (mbase + i * 16) * G_ + nbase + j * 16,
                                    acc[i][j], G_, wmma::mem_row_major);
}

// ---------------- kernel 2: fused 2-layer LSTM recurrence + output head ----------------
// R14 version (2 balanced barriers/step, fused P2b+P1(t+1), select-free reduces,
// x2-unrolled parities) + layer-1 bias folded at the P1 reduce (GEMM is bias-free).
__global__ __launch_bounds__(256, 1) void lstm_rec(
    const float* __restrict__ Whh1, const float* __restrict__ Wih2,
    const float* __restrict__ Whh2, const float* __restrict__ bih1,
    const float* __restrict__ bhh1, const float* __restrict__ bih2,
    const float* __restrict__ bhh2, const float* __restrict__ Wout,
    const float* __restrict__ bout, float* __restrict__ out) {
    __shared__ float h1s[2][2][64];   // [parity][row][unit]
    __shared__ float h2s[2][2][64];
    __shared__ float red[16];         // [warp][row]

    int tid = threadIdx.x;
    int q = tid >> 2, s = tid & 3;
    int myrow = s & 1;
    int prow = myrow ^ 1;

    // ---- weights into registers (gate-interleaved rows, k in [16s,16s+16)) ----
    u64 w1[4][8], w2i[4][8], w2h[4][8];
#pragma unroll
    for (int g = 0; g < 4; g++) {
        const u64* p;
        p = (const u64*)(Whh1 + (size_t)(g * 64 + q) * 64 + s * 16);
#pragma unroll
        for (int j = 0; j < 8; j++) w1[g][j] = p[j];
        p = (const u64*)(Wih2 + (size_t)(g * 64 + q) * 64 + s * 16);
#pragma unroll
        for (int j = 0; j < 8; j++) w2i[g][j] = p[j];
        p = (const u64*)(Whh2 + (size_t)(g * 64 + q) * 64 + s * 16);
#pragma unroll
        for (int j = 0; j < 8; j++) w2h[g][j] = p[j];
    }
    float b1v = bih1[s * 64 + q] + bhh1[s * 64 + q];   // layer-1 bias of gate s*64+q
    float b2v = bih2[s * 64 + q] + bhh2[s * 64 + q];   // layer-2 bias of gate s*64+q
    float wo = Wout[q];
    float bo = bout[0];
    float c1 = 0.0f, c2 = 0.0f;                        // carries for row = myrow

    int b0 = blockIdx.x * 2;
    // xp pointers swapped so xqo is always "my row", xqp the partner's
    const float* xprow0 = g_xp + (size_t)b0 * T_ * G_ + s * 64 + q;
    const float* xprow1 = xprow0 + (size_t)T_ * G_;
    const float* xpo = myrow ? xprow1 : xprow0;
    const float* xpp = myrow ? xprow0 : xprow1;
    float xqo = xpo[0];
    float xqp = xpp[0];

    if (tid < 128) {                  // zero parity-1 (prv at t=0)
        h1s[1][tid >> 6][tid & 63] = 0.0f;
        h2s[1][tid >> 6][tid & 63] = 0.0f;
    }
    __syncthreads();

    // ---- prologue: wv1(0). h = 0 so layer-1 gates(0) = xp(0)+bias1 distributed ----
    float wv1[4];
#pragma unroll
    for (int g = 0; g < 4; g++) {
        float fo = (s == g) ? (xqo + b1v) : 0.0f;
        float fp = (s == g) ? (xqp + b1v) : 0.0f;
        float tt = fo + __shfl_xor_sync(0xffffffffu, fp, 1);
        tt += __shfl_xor_sync(0xffffffffu, tt, 2);
        wv1[g] = tt;
    }

    auto step = [&](const int CUR, const int PRV, const int TT) {
        // ---- cell-1 update from carried wv1 -> h1(TT) ----
        float h1v;
        {
            float iv = sig_hw(wv1[0]), fv = sig_hw(wv1[1]);
            float gv = tanh_hw(wv1[2]), ov = sig_hw(wv1[3]);
            c1 = fv * c1 + iv * gv;
            h1v = ov * tanh_hw(c1);
        }

        // ---- P2a: layer-2 dots over h2 PREV (own/partner ordered) ----
        u64 a[8];   // [2g+0]=own row, [2g+1]=partner row
#pragma unroll
        for (int i = 0; i < 8; i++) a[i] = 0ull;
        {
            const ulonglong2* hO = (const ulonglong2*)&h2s[PRV][myrow][s * 16];
            const ulonglong2* hP = (const ulonglong2*)&h2s[PRV][prow][s * 16];
#pragma unroll
            for (int j = 0; j < 4; j++) {
                ulonglong2 zo = hO[j];
                ulonglong2 zp = hP[j];
#pragma unroll
                for (int g = 0; g < 4; g++) {
                    ffma2(a[2 * g + 0], w2h[g][2 * j], zo.x);
                    ffma2(a[2 * g + 0], w2h[g][2 * j + 1], zo.y);
                    ffma2(a[2 * g + 1], w2h[g][2 * j], zp.x);
                    ffma2(a[2 * g + 1], w2h[g][2 * j + 1], zp.y);
                }
            }
        }
        // prefetch xp(TT+1)
        if (TT + 1 < T_) {
            xpo += G_; xpp += G_;
            xqo = *xpo;
            xqp = *xpp;
        }
        if (s < 2) h1s[CUR][s][q] = h1v;     // lane s stores row s (= its myrow)
        __syncthreads();                     // B1: h1(CUR) visible

        // ---- fused pass over h1 NEW: P2b (into a) + P1(TT+1) (into b) ----
        u64 b[8];
#pragma unroll
        for (int i = 0; i < 8; i++) b[i] = 0ull;
        {
            const ulonglong2* hO = (const ulonglong2*)&h1s[CUR][myrow][s * 16];
            const ulonglong2* hP = (const ulonglong2*)&h1s[CUR][prow][s * 16];
#pragma unroll
            for (int j = 0; j < 4; j++) {
                ulonglong2 uo = hO[j];
                ulonglong2 up = hP[j];
#pragma unroll
                for (int g = 0; g < 4; g++) {
                    ffma2(a[2 * g + 0], w2i[g][2 * j], uo.x);
                    ffma2(a[2 * g + 0], w2i[g][2 * j + 1], uo.y);
                    ffma2(a[2 * g + 1], w2i[g][2 * j], up.x);
                    ffma2(a[2 * g + 1], w2i[g][2 * j + 1], up.y);
                }
#pragma unroll
                for (int g = 0; g < 4; g++) {
                    ffma2(b[2 * g + 0], w1[g][2 * j], uo.x);
                    ffma2(b[2 * g + 0], w1[g][2 * j + 1], uo.y);
                    ffma2(b[2 * g + 1], w1[g][2 * j], up.x);
                    ffma2(b[2 * g + 1], w1[g][2 * j + 1], up.y);
                }
            }
        }

        // ---- reduce a -> wv2(TT)  (bias2 folded pre-reduction, lane s==g) ----
        float wv2[4];
#pragma unroll
        for (int g = 0; g < 4; g++) {
            float bb = (s == g) ? b2v : 0.0f;
            float2 fo = unpk(a[2 * g + 0]);
            float2 fp = unpk(a[2 * g + 1]);
            float vo = fo.x + fo.y + bb;
            float vp = fp.x + fp.y + bb;
            float tt = vo + __shfl_xor_sync(0xffffffffu, vp, 1);
            tt += __shfl_xor_sync(0xffffffffu, tt, 2);
            wv2[g] = tt;
        }

        // ---- reduce b -> wv1(TT+1)  (xp + bias1 folded, lane s==g) ----
#pragma unroll
        for (int g = 0; g < 4; g++) {
            float2 fo = unpk(b[2 * g + 0]);
            float2 fp = unpk(b[2 * g + 1]);
            float vo = fo.x + fo.y + ((s == g) ? (xqo + b1v) : 0.0f);
            float vp = fp.x + fp.y + ((s == g) ? (xqp + b1v) : 0.0f);
            float tt = vo + __shfl_xor_sync(0xffffffffu, vp, 1);
            tt += __shfl_xor_sync(0xffffffffu, tt, 2);
            wv1[g] = tt;
        }

        // ---- cell-2 update + output head ----
        {
            float iv = sig_hw(wv2[0]), fv = sig_hw(wv2[1]);
            float gv = tanh_hw(wv2[2]), ov = sig_hw(wv2[3]);
            c2 = fv * c2 + iv * gv;
            float h2v = ov * tanh_hw(c2);
            if (s < 2) h2s[CUR][s][q] = h2v;
            float p = wo * h2v;
            p += __shfl_xor_sync(0xffffffffu, p, 4);
            p += __shfl_xor_sync(0xffffffffu, p, 8);
            p += __shfl_xor_sync(0xffffffffu, p, 16);
            if ((tid & 31) < 2) red[(tid >> 5) * 2 + s] = p;
        }
        __syncthreads();              // B2: h2(CUR) + red visible

        if (tid < 2) {
            float r = bo;
#pragma unroll
            for (int w = 0; w < 8; w++) r += red[w * 2 + tid];
            r = fminf(fmaxf(r, 0.0f), 1.0f);
            out[(size_t)(b0 + tid) * T_ + TT] = r;
        }
    };

    for (int tb = 0; tb < T_; tb += 2) {   // T_ even; parities literal
        step(0, 1, tb);
        step(1, 0, tb + 1);
    }
}

// ---------------- launch ----------------
extern "C" void kernel_launch(void* const* d_in, const int* in_sizes, int n_in,
                              void* d_out, int out_size) {
    const float* x    = (const float*)d_in[0];
    const float* Wih1 = (const float*)d_in[1];
    const float* Whh1 = (const float*)d_in[2];
    const float* bih1 = (const float*)d_in[3];
    const float* bhh1 = (const float*)d_in[4];
    const float* Wih2 = (const float*)d_in[5];
    const float* Whh2 = (const float*)d_in[6];
    const float* bih2 = (const float*)d_in[7];
    const float* bhh2 = (const float*)d_in[8];
    const float* Wout = (const float*)d_in[9];
    const float* bout = (const float*)d_in[10];
    float* out = (float*)d_out;

    xp_wmma<<<(B_ * T_) / 128, 256>>>(x, Wih1);
    lstm_rec<<<128, 256>>>(Whh1, Wih2, Whh2, bih1, bhh1, bih2, bhh2, Wout, bout, out);
    (void)in_sizes; (void)n_in; (void)out_size;
}

// round 16
// speedup vs baseline: 1.1447x; 1.0352x over previous
#include <cuda_runtime.h>
#include <cstdint>
#include <mma.h>

using namespace nvcuda;

#define B_   256
#define T_   2048
#define IN_  128
#define H_   64
#define G_   256   // 4*H
#define PIT  20    // smem pitch (floats): 80 B, 16B-aligned, conflict-breaking

// Scratch (allocation-free rule: static __device__ array)
__device__ float g_xp[(size_t)B_ * T_ * G_];   // x@W_ih1^T (NO bias — folded in lstm)

typedef unsigned long long u64;

// ---------------- helpers ----------------
__device__ __forceinline__ void ffma2(u64& d, u64 a, u64 b) {
    asm("fma.rn.f32x2 %0, %1, %2, %0;" : "+l"(d) : "l"(a), "l"(b));
}
__device__ __forceinline__ float2 unpk(u64 p) {
    float2 r;
    asm("mov.b64 {%0, %1}, %2;" : "=f"(r.x), "=f"(r.y) : "l"(p));
    return r;
}
__device__ __forceinline__ float tanh_hw(float x) {
    float r;
    asm("tanh.approx.f32 %0, %1;" : "=f"(r) : "f"(x));
    return r;
}
__device__ __forceinline__ float sig_hw(float x) {
    return fmaf(0.5f, tanh_hw(0.5f * x), 0.5f);
}

// ---------------- kernel 1: xp = x @ W_ih1^T  (tf32 wmma, smem-staged) ----------------
// M = B*T, N = 256, K = 128. 4096 blocks x 256 thr (8 warps).
// BM=128 (4 m-warps x 32 rows), BN=256 (2 n-warps x 128 cols).
// k processed in 16-wide chunks staged via smem (coalesced float4 LDG);
// fragment loads come from smem (LDS), not gmem. Same logical (row,col)
// mapping as the validated R15 kernel.
__global__ __launch_bounds__(256) void xp_wmma(const float* __restrict__ x,
                                               const float* __restrict__ W) {
    __shared__ float Xs[128][PIT];
    __shared__ float Ws[256][PIT];
    int tid = threadIdx.x;
    int wid = tid >> 5;
    int mwarp = wid >> 1, nwarp = wid & 1;
    size_t mbase = (size_t)blockIdx.x * 128;
    int mrow = mwarp * 32;
    int nbase = nwarp * 128;

    wmma::fragment<wmma::accumulator, 16, 16, 8, float> acc[2][8];
#pragma unroll
    for (int i = 0; i < 2; i++)
#pragma unroll
        for (int j = 0; j < 8; j++) wmma::fill_fragment(acc[i][j], 0.0f);

#pragma unroll
    for (int k0 = 0; k0 < IN_; k0 += 16) {
        __syncthreads();   // previous chunk's reads done before restage
        // stage Xs: 128 rows x 16 floats = 512 float4 (2 per thread)
#pragma unroll
        for (int i = 0; i < 2; i++) {
            int idx = tid + i * 256;
            int r = idx >> 2, c4 = (idx & 3) << 2;
            *(float4*)&Xs[r][c4] = *(const float4*)(x + (mbase + r) * IN_ + k0 + c4);
        }
        // stage Ws: 256 rows x 16 floats = 1024 float4 (4 per thread)
#pragma unroll
        for (int i = 0; i < 4; i++) {
            int idx = tid + i * 256;
            int r = idx >> 2, c4 = (idx & 3) << 2;
            *(float4*)&Ws[r][c4] = *(const float4*)(W + (size_t)r * IN_ + k0 + c4);
        }
        __syncthreads();

#pragma unroll
        for (int kk = 0; kk < 16; kk += 8) {
            wmma::fragment<wmma::matrix_a, 16, 16, 8, wmma::precision::tf32,
                           wmma::row_major> af[2];
            wmma::fragment<wmma::matrix_b, 16, 16, 8, wmma::precision::tf32,
                           wmma::col_major> bf[8];
#pragma unroll
            for (int i = 0; i < 2; i++) {
                wmma::load_matrix_sync(af[i], &Xs[mrow + i * 16][kk], PIT);
#pragma unroll
                for (int e = 0; e < af[i].num_elements; e++)
                    af[i].x[e] = wmma::__float_to_tf32(af[i].x[e]);
            }
#pragma unroll
            for (int j = 0; j < 8; j++) {
                wmma::load_matrix_sync(bf[j], &Ws[nbase + j * 16][kk], PIT);
#pragma unroll
                for (int e = 0; e < bf[j].num_elements; e++)
                    bf[j].x[e] = wmma::__float_to_tf32(bf[j].x[e]);
            }
#pragma unroll
            for (int i = 0; i < 2; i++)
#pragma unroll
                for (int j = 0; j < 8; j++)
                    wmma::mma_sync(acc[i][j], af[i], bf[j], acc[i][j]);
        }
    }

#pragma unroll
    for (int i = 0; i < 2; i++)
#pragma unroll
        for (int j = 0; j < 8; j++)
            wmma::store_matrix_sync(
                g_xp + (mbase + mrow + i * 16) * G_ + nbase + j * 16,
                acc[i][j], G_, wmma::mem_row_major);
}

// ---------------- kernel 2: fused 2-layer LSTM recurrence + output head ----------------
// (unchanged from R15 — R14 structure + bias1 folded at the P1 reduce)
__global__ __launch_bounds__(256, 1) void lstm_rec(
    const float* __restrict__ Whh1, const float* __restrict__ Wih2,
    const float* __restrict__ Whh2, const float* __restrict__ bih1,
    const float* __restrict__ bhh1, const float* __restrict__ bih2,
    const float* __restrict__ bhh2, const float* __restrict__ Wout,
    const float* __restrict__ bout, float* __restrict__ out) {
    __shared__ float h1s[2][2][64];   // [parity][row][unit]
    __shared__ float h2s[2][2][64];
    __shared__ float red[16];         // [warp][row]

    int tid = threadIdx.x;
    int q = tid >> 2, s = tid & 3;
    int myrow = s & 1;
    int prow = myrow ^ 1;

    u64 w1[4][8], w2i[4][8], w2h[4][8];
#pragma unroll
    for (int g = 0; g < 4; g++) {
        const u64* p;
        p = (const u64*)(Whh1 + (size_t)(g * 64 + q) * 64 + s * 16);
#pragma unroll
        for (int j = 0; j < 8; j++) w1[g][j] = p[j];
        p = (const u64*)(Wih2 + (size_t)(g * 64 + q) * 64 + s * 16);
#pragma unroll
        for (int j = 0; j < 8; j++) w2i[g][j] = p[j];
        p = (const u64*)(Whh2 + (size_t)(g * 64 + q) * 64 + s * 16);
#pragma unroll
        for (int j = 0; j < 8; j++) w2h[g][j] = p[j];
    }
    float b1v = bih1[s * 64 + q] + bhh1[s * 64 + q];
    float b2v = bih2[s * 64 + q] + bhh2[s * 64 + q];
    float wo = Wout[q];
    float bo = bout[0];
    float c1 = 0.0f, c2 = 0.0f;

    int b0 = blockIdx.x * 2;
    const float* xprow0 = g_xp + (size_t)b0 * T_ * G_ + s * 64 + q;
    const float* xprow1 = xprow0 + (size_t)T_ * G_;
    const float* xpo = myrow ? xprow1 : xprow0;
    const float* xpp = myrow ? xprow0 : xprow1;
    float xqo = xpo[0];
    float xqp = xpp[0];

    if (tid < 128) {
        h1s[1][tid >> 6][tid & 63] = 0.0f;
        h2s[1][tid >> 6][tid & 63] = 0.0f;
    }
    __syncthreads();

    float wv1[4];
#pragma unroll
    for (int g = 0; g < 4; g++) {
        float fo = (s == g) ? (xqo + b1v) : 0.0f;
        float fp = (s == g) ? (xqp + b1v) : 0.0f;
        float tt = fo + __shfl_xor_sync(0xffffffffu, fp, 1);
        tt += __shfl_xor_sync(0xffffffffu, tt, 2);
        wv1[g] = tt;
    }

    auto step = [&](const int CUR, const int PRV, const int TT) {
        float h1v;
        {
            float iv = sig_hw(wv1[0]), fv = sig_hw(wv1[1]);
            float gv = tanh_hw(wv1[2]), ov = sig_hw(wv1[3]);
            c1 = fv * c1 + iv * gv;
            h1v = ov * tanh_hw(c1);
        }

        u64 a[8];
#pragma unroll
        for (int i = 0; i < 8; i++) a[i] = 0ull;
        {
            const ulonglong2* hO = (const ulonglong2*)&h2s[PRV][myrow][s * 16];
            const ulonglong2* hP = (const ulonglong2*)&h2s[PRV][prow][s * 16];
#pragma unroll
            for (int j = 0; j < 4; j++) {
                ulonglong2 zo = hO[j];
                ulonglong2 zp = hP[j];
#pragma unroll
                for (int g = 0; g < 4; g++) {
                    ffma2(a[2 * g + 0], w2h[g][2 * j], zo.x);
                    ffma2(a[2 * g + 0], w2h[g][2 * j + 1], zo.y);
                    ffma2(a[2 * g + 1], w2h[g][2 * j], zp.x);
                    ffma2(a[2 * g + 1], w2h[g][2 * j + 1], zp.y);
                }
            }
        }
        if (TT + 1 < T_) {
            xpo += G_; xpp += G_;
            xqo = *xpo;
            xqp = *xpp;
        }
        if (s < 2) h1s[CUR][s][q] = h1v;
        __syncthreads();                     // B1

        u64 b[8];
#pragma unroll
        for (int i = 0; i < 8; i++) b[i] = 0ull;
        {
            const ulonglong2* hO = (const ulonglong2*)&h1s[CUR][myrow][s * 16];
            const ulonglong2* hP = (const ulonglong2*)&h1s[CUR][prow][s * 16];
#pragma unroll
            for (int j = 0; j < 4; j++) {
                ulonglong2 uo = hO[j];
                ulonglong2 up = hP[j];
#pragma unroll
                for (int g = 0; g < 4; g++) {
                    ffma2(a[2 * g + 0], w2i[g][2 * j], uo.x);
                    ffma2(a[2 * g + 0], w2i[g][2 * j + 1], uo.y);
                    ffma2(a[2 * g + 1], w2i[g][2 * j], up.x);
                    ffma2(a[2 * g + 1], w2i[g][2 * j + 1], up.y);
                }
#pragma unroll
                for (int g = 0; g < 4; g++) {
                    ffma2(b[2 * g + 0], w1[g][2 * j], uo.x);
                    ffma2(b[2 * g + 0], w1[g][2 * j + 1], uo.y);
                    ffma2(b[2 * g + 1], w1[g][2 * j], up.x);
                    ffma2(b[2 * g + 1], w1[g][2 * j + 1], up.y);
                }
            }
        }

        float wv2[4];
#pragma unroll
        for (int g = 0; g < 4; g++) {
            float bb = (s == g) ? b2v : 0.0f;
            float2 fo = unpk(a[2 * g + 0]);
            float2 fp = unpk(a[2 * g + 1]);
            float vo = fo.x + fo.y + bb;
            float vp = fp.x + fp.y + bb;
            float tt = vo + __shfl_xor_sync(0xffffffffu, vp, 1);
            tt += __shfl_xor_sync(0xffffffffu, tt, 2);
            wv2[g] = tt;
        }

#pragma unroll
        for (int g = 0; g < 4; g++) {
            float2 fo = unpk(b[2 * g + 0]);
            float2 fp = unpk(b[2 * g + 1]);
            float vo = fo.x + fo.y + ((s == g) ? (xqo + b1v) : 0.0f);
            float vp = fp.x + fp.y + ((s == g) ? (xqp + b1v) : 0.0f);
            float tt = vo + __shfl_xor_sync(0xffffffffu, vp, 1);
            tt += __shfl_xor_sync(0xffffffffu, tt, 2);
            wv1[g] = tt;
        }

        {
            float iv = sig_hw(wv2[0]), fv = sig_hw(wv2[1]);
            float gv = tanh_hw(wv2[2]), ov = sig_hw(wv2[3]);
            c2 = fv * c2 + iv * gv;
            float h2v = ov * tanh_hw(c2);
            if (s < 2) h2s[CUR][s][q] = h2v;
            float p = wo * h2v;
            p += __shfl_xor_sync(0xffffffffu, p, 4);
            p += __shfl_xor_sync(0xffffffffu, p, 8);
            p += __shfl_xor_sync(0xffffffffu, p, 16);
            if ((tid & 31) < 2) red[(tid >> 5) * 2 + s] = p;
        }
        __syncthreads();              // B2

        if (tid < 2) {
            float r = bo;
#pragma unroll
            for (int w = 0; w < 8; w++) r += red[w * 2 + tid];
            r = fminf(fmaxf(r, 0.0f), 1.0f);
            out[(size_t)(b0 + tid) * T_ + TT] = r;
        }
    };

    for (int tb = 0; tb < T_; tb += 2) {
        step(0, 1, tb);
        step(1, 0, tb + 1);
    }
}

// ---------------- launch ----------------
extern "C" void kernel_launch(void* const* d_in, const int* in_sizes, int n_in,
                              void* d_out, int out_size) {
    const float* x    = (const float*)d_in[0];
    const float* Wih1 = (const float*)d_in[1];
    const float* Whh1 = (const float*)d_in[2];
    const float* bih1 = (const float*)d_in[3];
    const float* bhh1 = (const float*)d_in[4];
    const float* Wih2 = (const float*)d_in[5];
    const float* Whh2 = (const float*)d_in[6];
    const float* bih2 = (const float*)d_in[7];
    const float* bhh2 = (const float*)d_in[8];
    const float* Wout = (const float*)d_in[9];
    const float* bout = (const float*)d_in[10];
    float* out = (float*)d_out;

    xp_wmma<<<(B_ * T_) / 128, 256>>>(x, Wih1);
    lstm_rec<<<128, 256>>>(Whh1, Wih2, Whh2, bih1, bhh1, bih2, bhh2, Wout, bout, out);
    (void)in_sizes; (void)n_in; (void)out_size;
}